// round 13
// baseline (speedup 1.0000x reference)
#include <cuda_runtime.h>
#include <math.h>
#include <stdint.h>

// Problem constants (fixed by the dataset)
#define NN      4096
#define MM      2048
#define DVV     3
#define DCC     6
#define EE      (NN*DVV)      // 12288
#define BB      2048
#define NITER   5
#define THREADS 1024
#define CN_T    (MM/THREADS)  // 2 CN tasks per thread (each covers 4 rows)
#define VN_T    (NN/THREADS)  // 4 VN tasks per thread

// SMEM: SoA msg planes: 3 planes of NN x f32x4 (16B) = 196608 B -> 1 CTA/SM
#define SMEM_BYTES (EE*16)

typedef unsigned long long ull;

// ---------------------------------------------------------------------------
// MUFU + pack helpers
// ---------------------------------------------------------------------------
__device__ __forceinline__ float ex2a(float x){ float r; asm("ex2.approx.ftz.f32 %0, %1;" : "=f"(r) : "f"(x)); return r; }
__device__ __forceinline__ float lg2a(float x){ float r; asm("lg2.approx.ftz.f32 %0, %1;" : "=f"(r) : "f"(x)); return r; }
__device__ __forceinline__ float rcpa(float x){ float r; asm("rcp.approx.ftz.f32 %0, %1;" : "=f"(r) : "f"(x)); return r; }
__device__ __forceinline__ ull  pk2(float a, float b){ ull r; asm("mov.b64 %0, {%1, %2};" : "=l"(r) : "f"(a), "f"(b)); return r; }
__device__ __forceinline__ void upk2(ull x, float& a, float& b){ asm("mov.b64 {%0, %1}, %2;" : "=f"(a), "=f"(b) : "l"(x)); }
__device__ __forceinline__ ull  fma2(ull a, ull b, ull c){ ull r; asm("fma.rn.f32x2 %0, %1, %2, %3;" : "=l"(r) : "l"(a), "l"(b), "l"(c)); return r; }
__device__ __forceinline__ ull  add2(ull a, ull b){ ull r; asm("add.rn.f32x2 %0, %1, %2;" : "=l"(r) : "l"(a), "l"(b)); return r; }

#define LOG2E_F 1.4426950408889634f
#define LN2_F   0.6931471805599453f
#define MAGMAX  16.635532f            /* 2*atanh(float(1-1e-7)): emulates CLIP    */
#define UMAX_F  0.99999988f           /* 1-2^-23: keeps 1-u and products nonzero  */
#define SIGN2   0x8000000080000000ull

// ---------------------------------------------------------------------------
// Persistent scratch (static globals: no runtime allocation)
// ---------------------------------------------------------------------------
__device__ int   g_cnt[MM];
__device__ int   g_tmp[EE];        // g_tmp[m*6+slot] = edge id (atomic order)
__device__ uint4 g_cnp[MM * 3];    // per CN: 6 x u32 SoA byte-offsets, 6 x f32 weights

// ---------------------------------------------------------------------------
// Prep kernels (deterministic after the sort)
// ---------------------------------------------------------------------------
__global__ void prep_zero()
{
    int i = blockIdx.x * blockDim.x + threadIdx.x;
    if (i < MM) g_cnt[i] = 0;
}

__global__ void prep_fill(const int* __restrict__ cn_idx)
{
    int e = blockIdx.x * blockDim.x + threadIdx.x;
    if (e < EE) {
        int m = cn_idx[e];
        int p = atomicAdd(&g_cnt[m], 1);
        g_tmp[m * DCC + p] = e;
    }
}

// SoA byte offset of edge e: plane (e%3), index (e/3), 16 bytes per entry
__device__ __forceinline__ unsigned soa_off(int e)
{
    return (unsigned)(((e % DVV) * NN + (e / DVV)) * 16);
}

__global__ void prep_pack(const float* __restrict__ w)
{
    int m = blockIdx.x * blockDim.x + threadIdx.x;
    if (m >= MM) return;
    int a[DCC];
#pragma unroll
    for (int j = 0; j < DCC; j++) a[j] = g_tmp[m * DCC + j];
    // sort ascending -> deterministic edge order matching jax scatter-add
#pragma unroll
    for (int i = 0; i < DCC - 1; i++)
#pragma unroll
        for (int j = 0; j < DCC - 1 - i; j++)
            if (a[j] > a[j + 1]) { int t = a[j]; a[j] = a[j + 1]; a[j + 1] = t; }

    uint4 p0, p1, p2;
    p0.x = soa_off(a[0]); p0.y = soa_off(a[1]);
    p0.z = soa_off(a[2]); p0.w = soa_off(a[3]);
    p1.x = soa_off(a[4]); p1.y = soa_off(a[5]);
    p1.z = __float_as_uint(w[a[0]]); p1.w = __float_as_uint(w[a[1]]);
    p2.x = __float_as_uint(w[a[2]]); p2.y = __float_as_uint(w[a[3]]);
    p2.z = __float_as_uint(w[a[4]]); p2.w = __float_as_uint(w[a[5]]);
    g_cnp[m * 3 + 0] = p0;
    g_cnp[m * 3 + 1] = p1;
    g_cnp[m * 3 + 2] = p2;
}

// ---------------------------------------------------------------------------
// Main BP kernel: one CTA per 4 batch rows, SoA msg planes (f32x4, 16B) in
// SMEM, product-domain CN update, llr pairs in registers. 1024 thr, 1 CTA/SM.
// ---------------------------------------------------------------------------
__global__ __launch_bounds__(THREADS, 1)
void bp_kernel(const float* __restrict__ noise_r,
               float* __restrict__ out)
{
    extern __shared__ unsigned char smem_raw[];
    uint4* P = reinterpret_cast<uint4*>(smem_raw);   // 3*NN entries of 16B

    const int tid  = threadIdx.x;
    const int rowA = blockIdx.x * 4;
    const float* nr0 = noise_r + (size_t)rowA * NN;

    const float NO_F = 0.3981071705534972f;   // 10^-0.4
    const float NSTD = 0.44615420f;           // sqrtf(no/2) in f32
    const ull   NEG1 = pk2(-1.0f, -1.0f);

    // llr for 4 rows per owned VN: two packed pairs each
    ull llr01[VN_T], llr23[VN_T];

    // ---- init: llr (regs) + msg planes (coalesced 16B stores) ----
#pragma unroll
    for (int k = 0; k < VN_T; ++k) {
        const int v = tid + k * THREADS;
        float l0 = (4.0f * (1.0f + NSTD * nr0[v + 0 * NN])) / NO_F;
        float l1 = (4.0f * (1.0f + NSTD * nr0[v + 1 * NN])) / NO_F;
        float l2 = (4.0f * (1.0f + NSTD * nr0[v + 2 * NN])) / NO_F;
        float l3 = (4.0f * (1.0f + NSTD * nr0[v + 3 * NN])) / NO_F;
        llr01[k] = pk2(l0, l1);
        llr23[k] = pk2(l2, l3);
        uint4 L = make_uint4(__float_as_uint(l0), __float_as_uint(l1),
                             __float_as_uint(l2), __float_as_uint(l3));
        P[v] = L; P[NN + v] = L; P[2 * NN + v] = L;
    }
    __syncthreads();

    for (int it = 0; it < NITER; ++it) {
        // ---- check-node pass: product-domain tanh BP, 4 rows per access ----
#pragma unroll
        for (int k = 0; k < CN_T; ++k) {
            const int m = tid + k * THREADS;
            const uint4 p0 = __ldg(&g_cnp[m * 3 + 0]);
            const uint4 p1 = __ldg(&g_cnp[m * 3 + 1]);
            const uint4 p2 = __ldg(&g_cnp[m * 3 + 2]);

            unsigned off[6] = { p0.x, p0.y, p0.z, p0.w, p1.x, p1.y };
            float    wgt[6] = { __uint_as_float(p1.z), __uint_as_float(p1.w),
                                __uint_as_float(p2.x), __uint_as_float(p2.y),
                                __uint_as_float(p2.z), __uint_as_float(p2.w) };

            ull      uab[6], ucd[6];
            unsigned sA = 0u, sB = 0u, sC = 0u, sD = 0u;
            ull Amab = pk2(1.0f, 1.0f), Bpab = pk2(1.0f, 1.0f);
            ull Amcd = pk2(1.0f, 1.0f), Bpcd = pk2(1.0f, 1.0f);
#pragma unroll
            for (int j = 0; j < 6; ++j) {
                const uint4 V = *reinterpret_cast<const uint4*>(smem_raw + off[j]);
                const float w = wgt[j];
                float xa = __uint_as_float(V.x) * w;
                float xb = __uint_as_float(V.y) * w;
                float xc = __uint_as_float(V.z) * w;
                float xd = __uint_as_float(V.w) * w;
                sA |= (__float_as_uint(xa) >> 31) << j;
                sB |= (__float_as_uint(xb) >> 31) << j;
                sC |= (__float_as_uint(xc) >> 31) << j;
                sD |= (__float_as_uint(xd) >> 31) << j;
                // u = e^{-|x|}  (tanh(|x|/2) = (1-u)/(1+u))
                float ua = fminf(ex2a(fabsf(xa) * -LOG2E_F), UMAX_F);
                float ub = fminf(ex2a(fabsf(xb) * -LOG2E_F), UMAX_F);
                float uc = fminf(ex2a(fabsf(xc) * -LOG2E_F), UMAX_F);
                float ud = fminf(ex2a(fabsf(xd) * -LOG2E_F), UMAX_F);
                uab[j] = pk2(ua, ub);
                ucd[j] = pk2(uc, ud);
                ull nab = uab[j] ^ SIGN2;
                ull ncd = ucd[j] ^ SIGN2;
                Amab = fma2(Amab, nab, Amab);      // *= (1-u), ascending order
                Bpab = fma2(Bpab, uab[j], Bpab);   // *= (1+u)
                Amcd = fma2(Amcd, ncd, Amcd);
                Bpcd = fma2(Bpcd, ucd[j], Bpcd);
            }
            float Aa, Ab, Ac, Ad, Ba, Bb, Bc, Bd;
            upk2(Amab, Aa, Ab); upk2(Bpab, Ba, Bb);
            upk2(Amcd, Ac, Ad); upk2(Bpcd, Bc, Bd);
            const float wa_ = Aa * rcpa(Ba);   // = prod tanh = e^{-S}
            const float wb_ = Ab * rcpa(Bb);
            const float wc_ = Ac * rcpa(Bc);
            const float wd_ = Ad * rcpa(Bd);
            const ull c1ab = pk2(1.0f + wa_, 1.0f + wb_);
            const ull c2ab = pk2(wa_ - 1.0f, wb_ - 1.0f);
            const ull c1cd = pk2(1.0f + wc_, 1.0f + wd_);
            const ull c2cd = pk2(wc_ - 1.0f, wd_ - 1.0f);
            const ull n1ab = c1ab ^ SIGN2, n2ab = c2ab ^ SIGN2;
            const ull n1cd = c1cd ^ SIGN2, n2cd = c2cd ^ SIGN2;
            const unsigned pA = __popc(sA) & 1u;
            const unsigned pB = __popc(sB) & 1u;
            const unsigned pC = __popc(sC) & 1u;
            const unsigned pD = __popc(sD) & 1u;
#pragma unroll
            for (int j = 0; j < 6; ++j) {
                // num = (1-u)+w(1+u) = c1+u*c2 ; den = (1-u)-w(1+u) = -c2-u*c1
                ull numab = fma2(uab[j], c2ab, c1ab);
                ull denab = fma2(uab[j], n1ab, n2ab);
                ull numcd = fma2(ucd[j], c2cd, c1cd);
                ull dencd = fma2(ucd[j], n1cd, n2cd);
                float na, nb, nc, nd, da, db, dc, dd;
                upk2(numab, na, nb); upk2(denab, da, db);
                upk2(numcd, nc, nd); upk2(dencd, dc, dd);
                da = fmaxf(da, 1e-30f);
                db = fmaxf(db, 1e-30f);
                dc = fmaxf(dc, 1e-30f);
                dd = fmaxf(dd, 1e-30f);
                float ga = fminf((lg2a(na) - lg2a(da)) * LN2_F, MAGMAX);
                float gb = fminf((lg2a(nb) - lg2a(db)) * LN2_F, MAGMAX);
                float gc = fminf((lg2a(nc) - lg2a(dc)) * LN2_F, MAGMAX);
                float gd = fminf((lg2a(nd) - lg2a(dd)) * LN2_F, MAGMAX);
                unsigned rA = __float_as_uint(ga) | ((pA ^ ((sA >> j) & 1u)) << 31);
                unsigned rB = __float_as_uint(gb) | ((pB ^ ((sB >> j) & 1u)) << 31);
                unsigned rC = __float_as_uint(gc) | ((pC ^ ((sC >> j) & 1u)) << 31);
                unsigned rD = __float_as_uint(gd) | ((pD ^ ((sD >> j) & 1u)) << 31);
                *reinterpret_cast<uint4*>(smem_raw + off[j]) = make_uint4(rA, rB, rC, rD);
            }
        }
        __syncthreads();

        // ---- variable-node pass: coalesced 16B SoA planes, llr in regs ----
        const bool last = (it == NITER - 1);
#pragma unroll
        for (int k = 0; k < VN_T; ++k) {
            const int v = tid + k * THREADS;
            uint4 M0 = P[v], M1 = P[NN + v], M2 = P[2 * NN + v];
            ull m0ab = pk2(__uint_as_float(M0.x), __uint_as_float(M0.y));
            ull m0cd = pk2(__uint_as_float(M0.z), __uint_as_float(M0.w));
            ull m1ab = pk2(__uint_as_float(M1.x), __uint_as_float(M1.y));
            ull m1cd = pk2(__uint_as_float(M1.z), __uint_as_float(M1.w));
            ull m2ab = pk2(__uint_as_float(M2.x), __uint_as_float(M2.y));
            ull m2cd = pk2(__uint_as_float(M2.z), __uint_as_float(M2.w));
            ull ltab = add2(llr01[k], add2(add2(m0ab, m1ab), m2ab));
            ull ltcd = add2(llr23[k], add2(add2(m0cd, m1cd), m2cd));
            if (last) {
                float t0, t1, t2, t3;
                upk2(ltab, t0, t1);
                upk2(ltcd, t2, t3);
                out[(size_t)(rowA + 0) * NN + v] = t0;
                out[(size_t)(rowA + 1) * NN + v] = t1;
                out[(size_t)(rowA + 2) * NN + v] = t2;
                out[(size_t)(rowA + 3) * NN + v] = t3;
            } else {
                ull q0ab = fma2(m0ab, NEG1, ltab), q0cd = fma2(m0cd, NEG1, ltcd);
                ull q1ab = fma2(m1ab, NEG1, ltab), q1cd = fma2(m1cd, NEG1, ltcd);
                ull q2ab = fma2(m2ab, NEG1, ltab), q2cd = fma2(m2cd, NEG1, ltcd);
                float a, b, c, d;
                upk2(q0ab, a, b); upk2(q0cd, c, d);
                P[v] = make_uint4(__float_as_uint(a), __float_as_uint(b),
                                  __float_as_uint(c), __float_as_uint(d));
                upk2(q1ab, a, b); upk2(q1cd, c, d);
                P[NN + v] = make_uint4(__float_as_uint(a), __float_as_uint(b),
                                       __float_as_uint(c), __float_as_uint(d));
                upk2(q2ab, a, b); upk2(q2cd, c, d);
                P[2 * NN + v] = make_uint4(__float_as_uint(a), __float_as_uint(b),
                                           __float_as_uint(c), __float_as_uint(d));
            }
        }
        __syncthreads();
    }
}

// ---------------------------------------------------------------------------
// Launch
// ---------------------------------------------------------------------------
extern "C" void kernel_launch(void* const* d_in, const int* in_sizes, int n_in,
                              void* d_out, int out_size)
{
    const float* noise_r = (const float*)d_in[0];
    // d_in[1] = noise_i (unused by the reference)
    const float* weights = (const float*)d_in[2];
    // d_in[3] = vn_idx (structural: e/3)
    const int*   cn_idx  = (const int*)d_in[4];
    float* out = (float*)d_out;

    (void)in_sizes; (void)n_in; (void)out_size;

    cudaFuncSetAttribute(bp_kernel, cudaFuncAttributeMaxDynamicSharedMemorySize, SMEM_BYTES);

    prep_zero<<<(MM + 255) / 256, 256>>>();
    prep_fill<<<(EE + 255) / 256, 256>>>(cn_idx);
    prep_pack<<<(MM + 255) / 256, 256>>>(weights);

    bp_kernel<<<BB / 4, THREADS, SMEM_BYTES>>>(noise_r, out);
}

// round 14
// speedup vs baseline: 1.4966x; 1.4966x over previous
#include <cuda_runtime.h>
#include <math.h>
#include <stdint.h>

// Problem constants (fixed by the dataset)
#define NN      4096
#define MM      2048
#define DVV     3
#define DCC     6
#define EE      (NN*DVV)      // 12288
#define BB      2048
#define NITER   5
#define THREADS 512
#define CN_T    (MM/THREADS)  // 4 CN tasks per thread (each covers 2 rows)
#define VN_T    (NN/THREADS)  // 8 VN tasks per thread

// SMEM: SoA msg planes: 3 planes of NN packed f32x2 = 98304 B -> 2 CTAs/SM
#define SMEM_BYTES (EE*8)

typedef unsigned long long ull;

// ---------------------------------------------------------------------------
// MUFU + pack helpers
// ---------------------------------------------------------------------------
__device__ __forceinline__ float ex2a(float x){ float r; asm("ex2.approx.ftz.f32 %0, %1;" : "=f"(r) : "f"(x)); return r; }
__device__ __forceinline__ float lg2a(float x){ float r; asm("lg2.approx.ftz.f32 %0, %1;" : "=f"(r) : "f"(x)); return r; }
__device__ __forceinline__ float rcpa(float x){ float r; asm("rcp.approx.ftz.f32 %0, %1;" : "=f"(r) : "f"(x)); return r; }
__device__ __forceinline__ ull  pk2(float a, float b){ ull r; asm("mov.b64 %0, {%1, %2};" : "=l"(r) : "f"(a), "f"(b)); return r; }
__device__ __forceinline__ void upk2(ull x, float& a, float& b){ asm("mov.b64 {%0, %1}, %2;" : "=f"(a), "=f"(b) : "l"(x)); }
__device__ __forceinline__ ull  fma2(ull a, ull b, ull c){ ull r; asm("fma.rn.f32x2 %0, %1, %2, %3;" : "=l"(r) : "l"(a), "l"(b), "l"(c)); return r; }
__device__ __forceinline__ ull  add2(ull a, ull b){ ull r; asm("add.rn.f32x2 %0, %1, %2;" : "=l"(r) : "l"(a), "l"(b)); return r; }

#define LOG2E_F 1.4426950408889634f
#define LN2_F   0.6931471805599453f
#define MAGMAX  16.635532f            /* 2*atanh(float(1-1e-7)): emulates CLIP    */
#define UMAX_F  0.99999988f           /* 1-2^-23: keeps 1-u and products nonzero  */

// ---------------------------------------------------------------------------
// Persistent scratch (static globals: no runtime allocation)
// ---------------------------------------------------------------------------
__device__ int g_cnt[MM];
__device__ int g_tmp[EE];          // g_tmp[m*6+slot] = edge id (atomic order)
__device__ ull g_ow[DCC * MM];     // SoA: plane j, CN m -> (u32 byte-offset | f32 weight << 32)

// ---------------------------------------------------------------------------
// Prep kernels (deterministic after the sort)
// ---------------------------------------------------------------------------
__global__ void prep_zero()
{
    int i = blockIdx.x * blockDim.x + threadIdx.x;
    if (i < MM) g_cnt[i] = 0;
}

__global__ void prep_fill(const int* __restrict__ cn_idx)
{
    int e = blockIdx.x * blockDim.x + threadIdx.x;
    if (e < EE) {
        int m = cn_idx[e];
        int p = atomicAdd(&g_cnt[m], 1);
        g_tmp[m * DCC + p] = e;
    }
}

// SoA byte offset of edge e: plane (e%3), index (e/3), 8 bytes per entry
__device__ __forceinline__ unsigned soa_off(int e)
{
    return (unsigned)(((e % DVV) * NN + (e / DVV)) * 8);
}

__global__ void prep_pack(const float* __restrict__ w)
{
    int m = blockIdx.x * blockDim.x + threadIdx.x;
    if (m >= MM) return;
    int a[DCC];
#pragma unroll
    for (int j = 0; j < DCC; j++) a[j] = g_tmp[m * DCC + j];
    // sort ascending -> deterministic edge order matching jax scatter-add
#pragma unroll
    for (int i = 0; i < DCC - 1; i++)
#pragma unroll
        for (int j = 0; j < DCC - 1 - i; j++)
            if (a[j] > a[j + 1]) { int t = a[j]; a[j] = a[j + 1]; a[j + 1] = t; }

    // SoA descriptor planes: coalesced 8B loads in the main kernel
#pragma unroll
    for (int j = 0; j < DCC; j++) {
        g_ow[j * MM + m] = (ull)soa_off(a[j]) |
                           ((ull)__float_as_uint(w[a[j]]) << 32);
    }
}

// ---------------------------------------------------------------------------
// Main BP kernel: one CTA per 2 batch rows, SoA msg planes (packed f32x2) in
// SMEM, product-domain CN update, SoA descriptors, llr pairs in registers.
// 2 CTAs/SM.
// ---------------------------------------------------------------------------
__global__ __launch_bounds__(THREADS, 2)
void bp_kernel(const float* __restrict__ noise_r,
               float* __restrict__ out)
{
    extern __shared__ ull smem8[];
    ull* P0 = smem8;            // plane 0: NN packed pairs
    ull* P1 = smem8 + NN;       // plane 1
    ull* P2 = smem8 + 2 * NN;   // plane 2

    const int tid  = threadIdx.x;
    const int rowA = blockIdx.x * 2;
    const float* nra = noise_r + (size_t)rowA * NN;
    const float* nrb = nra + NN;

    const float NO_F = 0.3981071705534972f;   // 10^-0.4
    const float NSTD = 0.44615420f;           // sqrtf(no/2) in f32
    const ull   NEG1 = pk2(-1.0f, -1.0f);

    // llr lives in registers: one packed pair per owned VN
    ull llr_r[VN_T];

    // ---- init: llr (regs) + msg planes (coalesced) ----
#pragma unroll
    for (int k = 0; k < VN_T; ++k) {
        const int v = tid + k * THREADS;
        float la = (4.0f * (1.0f + NSTD * nra[v])) / NO_F;
        float lb = (4.0f * (1.0f + NSTD * nrb[v])) / NO_F;
        ull l2 = pk2(la, lb);
        llr_r[k] = l2;
        P0[v] = l2;
        P1[v] = l2;
        P2[v] = l2;
    }
    __syncthreads();

    for (int it = 0; it < NITER; ++it) {
        // ---- check-node pass: product-domain tanh BP, both rows ----
#pragma unroll
        for (int k = 0; k < CN_T; ++k) {
            const int m = tid + k * THREADS;

            unsigned off[6];
            float    wgt[6];
#pragma unroll
            for (int j = 0; j < 6; ++j) {
                ull ow = __ldg(&g_ow[j * MM + m]);   // coalesced 8B, 2 lines/warp
                off[j] = (unsigned)ow;
                wgt[j] = __uint_as_float((unsigned)(ow >> 32));
            }

            float    ua[6], ub[6];
            unsigned sl = 0u, sh = 0u;   // per-row sign bitmasks (bit j)
            float Aa = 1.0f, Ba = 1.0f;  // prod (1-u), prod (1+u), row A
            float Ab = 1.0f, Bb = 1.0f;  // row B
#pragma unroll
            for (int j = 0; j < 6; ++j) {
                ull mm = *reinterpret_cast<const ull*>(
                             reinterpret_cast<const char*>(smem8) + off[j]);
                float xl, xh; upk2(mm, xl, xh);
                xl *= wgt[j];
                xh *= wgt[j];
                sl |= (__float_as_uint(xl) >> 31) << j;
                sh |= (__float_as_uint(xh) >> 31) << j;
                // u = e^{-|x|}  (so tanh(|x|/2) = (1-u)/(1+u))
                float va = ex2a(fabsf(xl) * -LOG2E_F);
                float vb = ex2a(fabsf(xh) * -LOG2E_F);
                va = fminf(va, UMAX_F);
                vb = fminf(vb, UMAX_F);
                ua[j] = va;  ub[j] = vb;
                Aa = fmaf(Aa, -va, Aa);  Ba = fmaf(Ba, va, Ba);
                Ab = fmaf(Ab, -vb, Ab);  Bb = fmaf(Bb, vb, Bb);
            }
            // w = prod tanh(|x_j|/2) = e^{-S}
            const float wa_ = Aa * rcpa(Ba);
            const float wb_ = Ab * rcpa(Bb);
            const float c1a = 1.0f + wa_, c2a = wa_ - 1.0f;
            const float c1b = 1.0f + wb_, c2b = wb_ - 1.0f;
            const unsigned pl = __popc(sl) & 1u;
            const unsigned ph = __popc(sh) & 1u;
#pragma unroll
            for (int j = 0; j < 6; ++j) {
                float va = ua[j], vb = ub[j];
                // z = w*(1+u)/(1-u);  mag = ln((1+z)/(1-z)) = 2*atanh(z)
                // num = (1-u) + w(1+u) = c1 + u*c2 ; den = (1-u) - w(1+u) = -c2 - u*c1
                float numa = fmaf(va,  c2a, c1a);
                float dena = fmaxf(fmaf(va, -c1a, -c2a), 1e-30f);
                float numb = fmaf(vb,  c2b, c1b);
                float denb = fmaxf(fmaf(vb, -c1b, -c2b), 1e-30f);
                float maga = fminf((lg2a(numa) - lg2a(dena)) * LN2_F, MAGMAX);
                float magb = fminf((lg2a(numb) - lg2a(denb)) * LN2_F, MAGMAX);
                unsigned rl = __float_as_uint(maga) | ((pl ^ ((sl >> j) & 1u)) << 31);
                unsigned rh = __float_as_uint(magb) | ((ph ^ ((sh >> j) & 1u)) << 31);
                *reinterpret_cast<ull*>(reinterpret_cast<char*>(smem8) + off[j]) =
                    pk2(__uint_as_float(rl), __uint_as_float(rh));
            }
        }
        __syncthreads();

        // ---- variable-node pass: coalesced SoA planes, llr from registers ----
        const bool last = (it == NITER - 1);
#pragma unroll
        for (int k = 0; k < VN_T; ++k) {
            const int v = tid + k * THREADS;
            ull m0 = P0[v];
            ull m1 = P1[v];
            ull m2 = P2[v];
            ull s  = add2(add2(m0, m1), m2);   // ascending edge order
            ull lt = add2(llr_r[k], s);
            if (last) {
                float a, b; upk2(lt, a, b);
                out[(size_t)rowA * NN + v]       = a;
                out[(size_t)(rowA + 1) * NN + v] = b;
            } else {
                P0[v] = fma2(m0, NEG1, lt);
                P1[v] = fma2(m1, NEG1, lt);
                P2[v] = fma2(m2, NEG1, lt);
            }
        }
        __syncthreads();
    }
}

// ---------------------------------------------------------------------------
// Launch
// ---------------------------------------------------------------------------
extern "C" void kernel_launch(void* const* d_in, const int* in_sizes, int n_in,
                              void* d_out, int out_size)
{
    const float* noise_r = (const float*)d_in[0];
    // d_in[1] = noise_i (unused by the reference)
    const float* weights = (const float*)d_in[2];
    // d_in[3] = vn_idx (structural: e/3)
    const int*   cn_idx  = (const int*)d_in[4];
    float* out = (float*)d_out;

    (void)in_sizes; (void)n_in; (void)out_size;

    cudaFuncSetAttribute(bp_kernel, cudaFuncAttributeMaxDynamicSharedMemorySize, SMEM_BYTES);

    prep_zero<<<(MM + 255) / 256, 256>>>();
    prep_fill<<<(EE + 255) / 256, 256>>>(cn_idx);
    prep_pack<<<(MM + 255) / 256, 256>>>(weights);

    bp_kernel<<<BB / 2, THREADS, SMEM_BYTES>>>(noise_r, out);
}

// round 15
// speedup vs baseline: 1.6587x; 1.1083x over previous
#include <cuda_runtime.h>
#include <math.h>
#include <stdint.h>

// Problem constants (fixed by the dataset)
#define NN      4096
#define MM      2048
#define DVV     3
#define DCC     6
#define EE      (NN*DVV)      // 12288
#define BB      2048
#define NITER   5
#define THREADS 512
#define CN_T    (MM/THREADS)  // 4 CN tasks per thread (each covers 2 rows)
#define VN_T    (NN/THREADS)  // 8 VN tasks per thread

// SMEM: SoA msg planes: 3 planes of NN packed f32x2 = 98304 B -> 2 CTAs/SM
#define SMEM_BYTES (EE*8)

typedef unsigned long long ull;

// ---------------------------------------------------------------------------
// MUFU + pack helpers
// ---------------------------------------------------------------------------
__device__ __forceinline__ float ex2a(float x){ float r; asm("ex2.approx.ftz.f32 %0, %1;" : "=f"(r) : "f"(x)); return r; }
__device__ __forceinline__ float lg2a(float x){ float r; asm("lg2.approx.ftz.f32 %0, %1;" : "=f"(r) : "f"(x)); return r; }
__device__ __forceinline__ float rcpa(float x){ float r; asm("rcp.approx.ftz.f32 %0, %1;" : "=f"(r) : "f"(x)); return r; }
__device__ __forceinline__ ull  pk2(float a, float b){ ull r; asm("mov.b64 %0, {%1, %2};" : "=l"(r) : "f"(a), "f"(b)); return r; }
__device__ __forceinline__ void upk2(ull x, float& a, float& b){ asm("mov.b64 {%0, %1}, %2;" : "=f"(a), "=f"(b) : "l"(x)); }
__device__ __forceinline__ ull  fma2(ull a, ull b, ull c){ ull r; asm("fma.rn.f32x2 %0, %1, %2, %3;" : "=l"(r) : "l"(a), "l"(b), "l"(c)); return r; }
__device__ __forceinline__ ull  mul2(ull a, ull b){ ull r; asm("mul.rn.f32x2 %0, %1, %2;" : "=l"(r) : "l"(a), "l"(b)); return r; }
__device__ __forceinline__ ull  add2(ull a, ull b){ ull r; asm("add.rn.f32x2 %0, %1, %2;" : "=l"(r) : "l"(a), "l"(b)); return r; }

#define LOG2E_F 1.4426950408889634f
#define LN2_F   0.6931471805599453f
#define MAGMAX  16.635532f            /* 2*atanh(float(1-1e-7)): emulates CLIP    */
#define UMAX_F  0.99999988f           /* 1-2^-23: keeps 1-u and products nonzero  */

// ---------------------------------------------------------------------------
// Persistent scratch (static globals: no runtime allocation)
// ---------------------------------------------------------------------------
__device__ int   g_cnt[MM];
__device__ int   g_tmp[EE];        // g_tmp[m*6+slot] = edge id (atomic order)
__device__ uint4 g_idx[MM];        // per CN: 6 x u16 plane-major edge indices (padded to 16B)
__device__ float g_wp[EE];         // plane-major weights: g_wp[(e%3)*NN + e/3] = w[e]

// ---------------------------------------------------------------------------
// Prep kernels (deterministic after the sort)
// ---------------------------------------------------------------------------
__global__ void prep_zero()
{
    int i = blockIdx.x * blockDim.x + threadIdx.x;
    if (i < MM) g_cnt[i] = 0;
}

__global__ void prep_fill(const int* __restrict__ cn_idx,
                          const float* __restrict__ w)
{
    int e = blockIdx.x * blockDim.x + threadIdx.x;
    if (e < EE) {
        int m = cn_idx[e];
        int p = atomicAdd(&g_cnt[m], 1);
        g_tmp[m * DCC + p] = e;
        g_wp[(e % DVV) * NN + (e / DVV)] = w[e];   // plane-major weights
    }
}

__global__ void prep_pack()
{
    int m = blockIdx.x * blockDim.x + threadIdx.x;
    if (m >= MM) return;
    int a[DCC];
#pragma unroll
    for (int j = 0; j < DCC; j++) a[j] = g_tmp[m * DCC + j];
    // sort ascending -> deterministic edge order matching jax scatter-add
#pragma unroll
    for (int i = 0; i < DCC - 1; i++)
#pragma unroll
        for (int j = 0; j < DCC - 1 - i; j++)
            if (a[j] > a[j + 1]) { int t = a[j]; a[j] = a[j + 1]; a[j + 1] = t; }

    // plane-major u16 indices: i = (e%3)*NN + e/3 (< 12288, fits u16)
    unsigned i0 = (unsigned)((a[0] % DVV) * NN + a[0] / DVV);
    unsigned i1 = (unsigned)((a[1] % DVV) * NN + a[1] / DVV);
    unsigned i2 = (unsigned)((a[2] % DVV) * NN + a[2] / DVV);
    unsigned i3 = (unsigned)((a[3] % DVV) * NN + a[3] / DVV);
    unsigned i4 = (unsigned)((a[4] % DVV) * NN + a[4] / DVV);
    unsigned i5 = (unsigned)((a[5] % DVV) * NN + a[5] / DVV);
    uint4 q;
    q.x = i0 | (i1 << 16);
    q.y = i2 | (i3 << 16);
    q.z = i4 | (i5 << 16);
    q.w = 0;
    g_idx[m] = q;
}

// ---------------------------------------------------------------------------
// Main BP kernel: one CTA per 2 batch rows, SoA msg planes (packed f32x2) in
// SMEM holding PRE-WEIGHTED vn messages; product-domain CN update with 16B/CN
// descriptors; llr pairs in registers. 2 CTAs/SM.
// ---------------------------------------------------------------------------
__global__ __launch_bounds__(THREADS, 2)
void bp_kernel(const float* __restrict__ noise_r,
               float* __restrict__ out)
{
    extern __shared__ ull smem8[];
    ull* P0 = smem8;            // plane 0: NN packed pairs
    ull* P1 = smem8 + NN;       // plane 1
    ull* P2 = smem8 + 2 * NN;   // plane 2

    const int tid  = threadIdx.x;
    const int rowA = blockIdx.x * 2;
    const float* nra = noise_r + (size_t)rowA * NN;
    const float* nrb = nra + NN;

    const float NO_F = 0.3981071705534972f;   // 10^-0.4
    const float NSTD = 0.44615420f;           // sqrtf(no/2) in f32
    const ull   NEG1 = pk2(-1.0f, -1.0f);

    // llr lives in registers: one packed pair per owned VN
    ull llr_r[VN_T];

    // ---- init: llr (regs) + PRE-WEIGHTED msg planes (coalesced) ----
#pragma unroll
    for (int k = 0; k < VN_T; ++k) {
        const int v = tid + k * THREADS;
        float la = (4.0f * (1.0f + NSTD * nra[v])) / NO_F;
        float lb = (4.0f * (1.0f + NSTD * nrb[v])) / NO_F;
        ull l2 = pk2(la, lb);
        llr_r[k] = l2;
        float w0 = __ldg(&g_wp[0 * NN + v]);
        float w1 = __ldg(&g_wp[1 * NN + v]);
        float w2 = __ldg(&g_wp[2 * NN + v]);
        P0[v] = mul2(l2, pk2(w0, w0));
        P1[v] = mul2(l2, pk2(w1, w1));
        P2[v] = mul2(l2, pk2(w2, w2));
    }
    __syncthreads();

    for (int it = 0; it < NITER; ++it) {
        // ---- check-node pass: product-domain tanh BP, both rows ----
#pragma unroll
        for (int k = 0; k < CN_T; ++k) {
            const int m = tid + k * THREADS;
            const uint4 q = __ldg(&g_idx[m]);   // 16B/CN: 6 x u16 indices

            unsigned off[6];
            off[0] = (q.x & 0xFFFFu) * 8;  off[1] = (q.x >> 16) * 8;
            off[2] = (q.y & 0xFFFFu) * 8;  off[3] = (q.y >> 16) * 8;
            off[4] = (q.z & 0xFFFFu) * 8;  off[5] = (q.z >> 16) * 8;

            float    ua[6], ub[6];
            unsigned sl = 0u, sh = 0u;   // per-row sign bitmasks (bit j)
            float Aa = 1.0f, Ba = 1.0f;  // prod (1-u), prod (1+u), row A
            float Ab = 1.0f, Bb = 1.0f;  // row B
#pragma unroll
            for (int j = 0; j < 6; ++j) {
                ull mm = *reinterpret_cast<const ull*>(
                             reinterpret_cast<const char*>(smem8) + off[j]);
                float xl, xh; upk2(mm, xl, xh);   // already weighted
                sl |= (__float_as_uint(xl) >> 31) << j;
                sh |= (__float_as_uint(xh) >> 31) << j;
                // u = e^{-|x|}  (so tanh(|x|/2) = (1-u)/(1+u))
                float va = ex2a(fabsf(xl) * -LOG2E_F);
                float vb = ex2a(fabsf(xh) * -LOG2E_F);
                va = fminf(va, UMAX_F);
                vb = fminf(vb, UMAX_F);
                ua[j] = va;  ub[j] = vb;
                Aa = fmaf(Aa, -va, Aa);  Ba = fmaf(Ba, va, Ba);
                Ab = fmaf(Ab, -vb, Ab);  Bb = fmaf(Bb, vb, Bb);
            }
            // w = prod tanh(|x_j|/2) = e^{-S}
            const float wa_ = Aa * rcpa(Ba);
            const float wb_ = Ab * rcpa(Bb);
            const float c1a = 1.0f + wa_, c2a = wa_ - 1.0f;
            const float c1b = 1.0f + wb_, c2b = wb_ - 1.0f;
            const unsigned pl = __popc(sl) & 1u;
            const unsigned ph = __popc(sh) & 1u;
#pragma unroll
            for (int j = 0; j < 6; ++j) {
                float va = ua[j], vb = ub[j];
                // z = w*(1+u)/(1-u);  mag = ln((1+z)/(1-z)) = 2*atanh(z)
                // num = (1-u) + w(1+u) = c1 + u*c2 ; den = (1-u) - w(1+u) = -c2 - u*c1
                float numa = fmaf(va,  c2a, c1a);
                float dena = fmaxf(fmaf(va, -c1a, -c2a), 1e-30f);
                float numb = fmaf(vb,  c2b, c1b);
                float denb = fmaxf(fmaf(vb, -c1b, -c2b), 1e-30f);
                float maga = fminf((lg2a(numa) - lg2a(dena)) * LN2_F, MAGMAX);
                float magb = fminf((lg2a(numb) - lg2a(denb)) * LN2_F, MAGMAX);
                unsigned rl = __float_as_uint(maga) | ((pl ^ ((sl >> j) & 1u)) << 31);
                unsigned rh = __float_as_uint(magb) | ((ph ^ ((sh >> j) & 1u)) << 31);
                *reinterpret_cast<ull*>(reinterpret_cast<char*>(smem8) + off[j]) =
                    pk2(__uint_as_float(rl), __uint_as_float(rh));
            }
        }
        __syncthreads();

        // ---- variable-node pass: coalesced SoA planes; re-weight on store ----
        const bool last = (it == NITER - 1);
#pragma unroll
        for (int k = 0; k < VN_T; ++k) {
            const int v = tid + k * THREADS;
            ull m0 = P0[v];      // unweighted msg_cn from the CN pass
            ull m1 = P1[v];
            ull m2 = P2[v];
            ull s  = add2(add2(m0, m1), m2);   // ascending edge order
            ull lt = add2(llr_r[k], s);
            if (last) {
                float a, b; upk2(lt, a, b);
                out[(size_t)rowA * NN + v]       = a;
                out[(size_t)(rowA + 1) * NN + v] = b;
            } else {
                float w0 = __ldg(&g_wp[0 * NN + v]);
                float w1 = __ldg(&g_wp[1 * NN + v]);
                float w2 = __ldg(&g_wp[2 * NN + v]);
                P0[v] = mul2(fma2(m0, NEG1, lt), pk2(w0, w0));
                P1[v] = mul2(fma2(m1, NEG1, lt), pk2(w1, w1));
                P2[v] = mul2(fma2(m2, NEG1, lt), pk2(w2, w2));
            }
        }
        __syncthreads();
    }
}

// ---------------------------------------------------------------------------
// Launch
// ---------------------------------------------------------------------------
extern "C" void kernel_launch(void* const* d_in, const int* in_sizes, int n_in,
                              void* d_out, int out_size)
{
    const float* noise_r = (const float*)d_in[0];
    // d_in[1] = noise_i (unused by the reference)
    const float* weights = (const float*)d_in[2];
    // d_in[3] = vn_idx (structural: e/3)
    const int*   cn_idx  = (const int*)d_in[4];
    float* out = (float*)d_out;

    (void)in_sizes; (void)n_in; (void)out_size;

    cudaFuncSetAttribute(bp_kernel, cudaFuncAttributeMaxDynamicSharedMemorySize, SMEM_BYTES);

    prep_zero<<<(MM + 255) / 256, 256>>>();
    prep_fill<<<(EE + 255) / 256, 256>>>(cn_idx, weights);
    prep_pack<<<(MM + 255) / 256, 256>>>();

    bp_kernel<<<BB / 2, THREADS, SMEM_BYTES>>>(noise_r, out);
}